// round 3
// baseline (speedup 1.0000x reference)
#include <cuda_runtime.h>

#define BB 4
#define NN 10000
#define DD 256
#define MM (BB*NN)
#define EE 160000
#define NCHUNK 64
#define CHUNK_SZ 157  /* 64*157 = 10048 >= 10000 */

// ---------------- scratch (static device memory; no runtime allocs) ----------
__device__ __align__(16) float g_bufA[(size_t)MM * DD];
__device__ __align__(16) float g_bufB[(size_t)MM * DD];
__device__ __align__(16) float g_bufC[(size_t)MM * DD];
__device__ int   g_deg[NN];
__device__ int   g_off[NN + 1];
__device__ int   g_cursor[NN];
__device__ int   g_eidx[EE];
__device__ float g_score[MM];
__device__ float g_alpha[MM];
__device__ float g_r[BB * DD];
__device__ float g_rpart[BB * NCHUNK * DD];

// ---------------- CSR build --------------------------------------------------
__global__ void k_zero_csr() {
    int i = blockIdx.x * blockDim.x + threadIdx.x;
    if (i < NN) { g_deg[i] = 0; g_cursor[i] = 0; }
}

__global__ void k_degree(const int* __restrict__ dst, int E) {
    int e = blockIdx.x * blockDim.x + threadIdx.x;
    if (e < E) atomicAdd(&g_deg[dst[e]], 1);
}

// one-block exclusive scan over NN=10000 (1000 threads x 10 elems)
__global__ void k_scan() {
    __shared__ int tsums[1024];
    int t = threadIdx.x;
    int local[10];
    int s = 0;
    if (t < 1000) {
        int base = t * 10;
#pragma unroll
        for (int i = 0; i < 10; i++) { local[i] = g_deg[base + i]; s += local[i]; }
    }
    tsums[t] = (t < 1000) ? s : 0;
    __syncthreads();
    for (int off = 1; off < 1024; off <<= 1) {
        int v = (t >= off) ? tsums[t - off] : 0;
        __syncthreads();
        tsums[t] += v;
        __syncthreads();
    }
    if (t < 1000) {
        int run = (t == 0) ? 0 : tsums[t - 1];
        int base = t * 10;
#pragma unroll
        for (int i = 0; i < 10; i++) { g_off[base + i] = run; run += local[i]; }
    }
    if (t == 0) g_off[NN] = tsums[1023];
}

__global__ void k_fill(const int* __restrict__ src, const int* __restrict__ dst, int E) {
    int e = blockIdx.x * blockDim.x + threadIdx.x;
    if (e < E) {
        int d = dst[e];
        int p = atomicAdd(&g_cursor[d], 1);
        g_eidx[g_off[d] + p] = src[e];
    }
}

// ---------------- generic SGEMM: C = A(MxK) @ B(KxN) [+bias][+relu] ----------
// requires M%64==0, N%64==0, K%16==0
__global__ void k_gemm(const float* __restrict__ A, const float* __restrict__ B,
                       const float* __restrict__ bias, float* __restrict__ C,
                       int M, int N, int K, int act) {
    __shared__ __align__(16) float As[16][64];
    __shared__ __align__(16) float Bs[16][64];
    int bm = blockIdx.y * 64, bn = blockIdx.x * 64;
    int tid = threadIdx.x;
    int tx = tid & 15, ty = tid >> 4;

    const int ar = tid >> 2;            // 0..63  (A row within tile)
    const int ac = (tid & 3) << 2;      // 0,4,8,12 (A col within ktile)
    const int br = tid >> 4;            // 0..15  (B row within ktile)
    const int bc = (tid & 15) << 2;     // 0..60  (B col within tile)

    float acc[4][4] = {};

    for (int k0 = 0; k0 < K; k0 += 16) {
        float4 av = *(const float4*)(A + (size_t)(bm + ar) * K + k0 + ac);
        float4 bv = *(const float4*)(B + (size_t)(k0 + br) * N + bn + bc);
        As[ac + 0][ar] = av.x;
        As[ac + 1][ar] = av.y;
        As[ac + 2][ar] = av.z;
        As[ac + 3][ar] = av.w;
        *(float4*)&Bs[br][bc] = bv;
        __syncthreads();
#pragma unroll
        for (int kk = 0; kk < 16; kk++) {
            float4 a4 = *(const float4*)&As[kk][ty << 2];
            float4 b4 = *(const float4*)&Bs[kk][tx << 2];
            float avv[4] = {a4.x, a4.y, a4.z, a4.w};
            float bvv[4] = {b4.x, b4.y, b4.z, b4.w};
#pragma unroll
            for (int i = 0; i < 4; i++)
#pragma unroll
                for (int j = 0; j < 4; j++) acc[i][j] += avv[i] * bvv[j];
        }
        __syncthreads();
    }

#pragma unroll
    for (int i = 0; i < 4; i++) {
        int row = bm + (ty << 2) + i;
        int col = bn + (tx << 2);
        float o[4];
#pragma unroll
        for (int j = 0; j < 4; j++) {
            float v = acc[i][j];
            if (bias) v += bias[col + j];
            if (act == 1) v = fmaxf(v, 0.0f);
            o[j] = v;
        }
        *(float4*)(C + (size_t)row * N + col) = make_float4(o[0], o[1], o[2], o[3]);
    }
}

// ---------------- GCN aggregation + bias + exact GELU ------------------------
__global__ void k_agg_gelu(const float* __restrict__ sup, const float* __restrict__ bias,
                           float* __restrict__ out) {
    int n = blockIdx.x, b = blockIdx.y, h = threadIdx.x;
    int s = g_off[n], e = g_off[n + 1];
    const float* base = sup + (size_t)b * NN * DD;
    float acc = 0.0f;
    for (int j = s; j < e; j++) acc += base[(size_t)g_eidx[j] * DD + h];
    float v = acc + bias[h];
    out[((size_t)b * NN + n) * DD + h] = 0.5f * v * (1.0f + erff(v * 0.70710678118654752f));
}

// ---------------- attention pool pieces ---------------------------------------
__global__ void k_attn_score(const float* __restrict__ x, const float* __restrict__ W,
                             const float* __restrict__ u) {
    int warp = threadIdx.x >> 5, lane = threadIdx.x & 31;
    int idx = blockIdx.x * 8 + warp;  // < MM
    const float* xr = x + (size_t)idx * DD;
    float acc[8] = {0, 0, 0, 0, 0, 0, 0, 0};
    for (int d = lane; d < DD; d += 32) {
        float xv = xr[d];
#pragma unroll
        for (int k = 0; k < 8; k++) acc[k] += xv * W[d * 8 + k];
    }
#pragma unroll
    for (int k = 0; k < 8; k++)
#pragma unroll
        for (int o = 16; o > 0; o >>= 1) acc[k] += __shfl_xor_sync(0xffffffffu, acc[k], o);
    if (lane == 0) {
        float s = 0.0f;
#pragma unroll
        for (int k = 0; k < 8; k++) s += tanhf(acc[k]) * u[k];
        g_score[idx] = s;
    }
}

__global__ void k_dot_r(const float* __restrict__ x) {
    int warp = threadIdx.x >> 5, lane = threadIdx.x & 31;
    int idx = blockIdx.x * 8 + warp;
    int b = idx / NN;
    const float* xr = x + (size_t)idx * DD;
    const float* rr = g_r + b * DD;
    float acc = 0.0f;
    for (int d = lane; d < DD; d += 32) acc += xr[d] * rr[d];
#pragma unroll
    for (int o = 16; o > 0; o >>= 1) acc += __shfl_xor_sync(0xffffffffu, acc, o);
    if (lane == 0) g_score[idx] = acc;
}

__global__ void k_softmax() {
    int b = blockIdx.x, t = threadIdx.x;
    __shared__ float sh[32];
    const float* sc = g_score + b * NN;

    float m = -1e30f;
    for (int n = t; n < NN; n += 1024) m = fmaxf(m, sc[n]);
#pragma unroll
    for (int o = 16; o > 0; o >>= 1) m = fmaxf(m, __shfl_xor_sync(0xffffffffu, m, o));
    if ((t & 31) == 0) sh[t >> 5] = m;
    __syncthreads();
    float mm = -1e30f;
#pragma unroll
    for (int i = 0; i < 32; i++) mm = fmaxf(mm, sh[i]);
    __syncthreads();

    float s = 0.0f;
    for (int n = t; n < NN; n += 1024) s += expf(sc[n] - mm);
#pragma unroll
    for (int o = 16; o > 0; o >>= 1) s += __shfl_xor_sync(0xffffffffu, s, o);
    if ((t & 31) == 0) sh[t >> 5] = s;
    __syncthreads();
    float tot = 0.0f;
#pragma unroll
    for (int i = 0; i < 32; i++) tot += sh[i];
    float inv = 1.0f / tot;

    for (int n = t; n < NN; n += 1024) g_alpha[b * NN + n] = expf(sc[n] - mm) * inv;
}

__global__ void k_wsum(const float* __restrict__ x, int use_alpha) {
    int c = blockIdx.x, b = blockIdx.y, d = threadIdx.x;
    int n0 = c * CHUNK_SZ;
    int n1 = n0 + CHUNK_SZ;
    if (n1 > NN) n1 = NN;
    float acc = 0.0f;
    for (int n = n0; n < n1; n++) {
        float w = use_alpha ? g_alpha[b * NN + n] : 1.0f;
        acc += w * x[((size_t)b * NN + n) * DD + d];
    }
    g_rpart[((size_t)b * NCHUNK + c) * DD + d] = acc;
}

__global__ void k_reduce_r(float scale) {
    int b = blockIdx.x, d = threadIdx.x;
    float s = 0.0f;
    for (int c = 0; c < NCHUNK; c++) s += g_rpart[((size_t)b * NCHUNK + c) * DD + d];
    g_r[b * DD + d] = s * scale;
}

// ---------------- add + layernorm ---------------------------------------------
__device__ __forceinline__ float blk_sum256(float v) {
    __shared__ float sh[8];
#pragma unroll
    for (int o = 16; o > 0; o >>= 1) v += __shfl_xor_sync(0xffffffffu, v, o);
    if ((threadIdx.x & 31) == 0) sh[threadIdx.x >> 5] = v;
    __syncthreads();
    float t = 0.0f;
#pragma unroll
    for (int i = 0; i < 8; i++) t += sh[i];
    __syncthreads();
    return t;
}

__global__ void k_add_ln(const float* __restrict__ x, const float* __restrict__ h, int use_r,
                         const float* __restrict__ g, const float* __restrict__ bb,
                         float* __restrict__ out) {
    int idx = blockIdx.x;
    int b = idx / NN;
    int d = threadIdx.x;
    float addv;
    if (use_r) addv = g_r[b * DD + d];
    else       addv = h[(size_t)idx * DD + d];
    float v = x[(size_t)idx * DD + d] + addv;
    float mu = blk_sum256(v) * (1.0f / DD);
    float dv = v - mu;
    float var = blk_sum256(dv * dv) * (1.0f / DD);
    out[(size_t)idx * DD + d] = dv * rsqrtf(var + 1e-5f) * g[d] + bb[d];
}

// ---------------- final FC on mean(x) ------------------------------------------
__global__ void k_fc(const float* __restrict__ fcW, const float* __restrict__ fcb,
                     float* __restrict__ out) {
    int t = threadIdx.x;
    if (t < BB * 10) {
        int b = t / 10, o = t % 10;
        float s = fcb[o];
        for (int d = 0; d < DD; d++) s += g_r[b * DD + d] * fcW[d * 10 + o];
        out[t] = s;
    }
}

// ---------------- launch ---------------------------------------------------------
extern "C" void kernel_launch(void* const* d_in, const int* in_sizes, int n_in,
                              void* d_out, int out_size) {
    const float* x_in    = (const float*)d_in[0];
    const int*   src     = (const int*)d_in[1];
    const int*   dst     = (const int*)d_in[2];
    const float* W_conv0 = (const float*)d_in[3];
    const float* b_conv0 = (const float*)d_in[4];
    const float* W_convs = (const float*)d_in[5];
    const float* b_convs = (const float*)d_in[6];
    const float* mW1 = (const float*)d_in[7];
    const float* mb1 = (const float*)d_in[8];
    const float* mW2 = (const float*)d_in[9];
    const float* mb2 = (const float*)d_in[10];
    const float* mW3 = (const float*)d_in[11];
    const float* mb3 = (const float*)d_in[12];
    const float* ln1_g = (const float*)d_in[13];
    const float* ln1_b = (const float*)d_in[14];
    const float* ln2_g = (const float*)d_in[15];
    const float* ln2_b = (const float*)d_in[16];
    const float* attnW = (const float*)d_in[17];
    const float* attnu = (const float*)d_in[18];
    const float* fW1 = (const float*)d_in[19];
    const float* fb1 = (const float*)d_in[20];
    const float* fW2 = (const float*)d_in[21];
    const float* fb2 = (const float*)d_in[22];
    const float* fcW = (const float*)d_in[23];
    const float* fcb = (const float*)d_in[24];
    float* out = (float*)d_out;
    int E = in_sizes[1];

    float *bufA, *bufB, *bufC;
    cudaGetSymbolAddress((void**)&bufA, g_bufA);
    cudaGetSymbolAddress((void**)&bufB, g_bufB);
    cudaGetSymbolAddress((void**)&bufC, g_bufC);

    // ---- CSR build (by dst) ----
    k_zero_csr<<<(NN + 255) / 256, 256>>>();
    k_degree<<<(E + 255) / 256, 256>>>(dst, E);
    k_scan<<<1, 1024>>>();
    k_fill<<<(E + 255) / 256, 256>>>(src, dst, E);

    dim3 gemm256(256 / 64, MM / 64);
    dim3 gemm128(128 / 64, MM / 64);
    dim3 gemm64(64 / 64, MM / 64);
    dim3 aggGrid(NN, BB);

    // ---- GCN stack ----
    k_gemm<<<gemm256, 256>>>(x_in, W_conv0, nullptr, bufB, MM, 256, 128, 0);
    k_agg_gelu<<<aggGrid, 256>>>(bufB, b_conv0, bufA);
    for (int i = 0; i < 3; i++) {
        k_gemm<<<gemm256, 256>>>(bufA, W_convs + (size_t)i * 256 * 256, nullptr, bufB,
                                 MM, 256, 256, 0);
        k_agg_gelu<<<aggGrid, 256>>>(bufB, b_convs + i * 256, bufA);
    }

    // ---- MLP ----
    k_gemm<<<gemm128, 256>>>(bufA, mW1, mb1, bufB, MM, 128, 256, 1);
    k_gemm<<<gemm64, 256>>>(bufB, mW2, mb2, bufC, MM, 64, 128, 1);
    k_gemm<<<gemm256, 256>>>(bufC, mW3, mb3, bufA, MM, 256, 64, 0);

    // ---- 2 pooled residual blocks ----
    float* cur = bufA;
    float* o1 = bufB;
    float* o2 = bufC;
    for (int i = 0; i < 2; i++) {
        // attention pool
        k_attn_score<<<MM / 8, 256>>>(cur, attnW + (size_t)i * DD * 8, attnu + i * 8);
        k_softmax<<<BB, 1024>>>();
        k_wsum<<<dim3(NCHUNK, BB), 256>>>(cur, 1);
        k_reduce_r<<<BB, 256>>>(1.0f);
        for (int it = 0; it < 3; it++) {
            k_dot_r<<<MM / 8, 256>>>(cur);
            k_softmax<<<BB, 1024>>>();
            k_wsum<<<dim3(NCHUNK, BB), 256>>>(cur, 1);
            k_reduce_r<<<BB, 256>>>(1.0f);
        }
        // x = LN(x + r)
        k_add_ln<<<MM, 256>>>(cur, cur /*unused*/, 1, ln1_g + i * DD, ln1_b + i * DD, o1);
        // FFN
        k_gemm<<<gemm256, 256>>>(o1, fW1 + (size_t)i * DD * 256, fb1 + i * 256, o2,
                                 MM, 256, 256, 1);
        k_gemm<<<gemm256, 256>>>(o2, fW2 + (size_t)i * 256 * DD, fb2 + i * DD, cur,
                                 MM, 256, 256, 0);
        // x = LN(x + h)  — reads o1 (residual) + cur (h), writes o2
        k_add_ln<<<MM, 256>>>(o1, cur, 0, ln2_g + i * DD, ln2_b + i * DD, o2);
        // rotate: new cur = o2, old cur becomes scratch
        float* t = cur; cur = o2; o2 = t;
    }

    // ---- final: out = mean_n(x) @ fcW + fcb ----
    k_wsum<<<dim3(NCHUNK, BB), 256>>>(cur, 0);
    k_reduce_r<<<BB, 256>>>(1.0f / (float)NN);
    k_fc<<<1, 64>>>(fcW, fcb, out);
}

// round 4
// speedup vs baseline: 1.0018x; 1.0018x over previous
#include <cuda_runtime.h>

#define BB 4
#define NN 10000
#define DD 256
#define MM (BB*NN)
#define EE 160000
#define NCHUNK 64
#define CHUNK_SZ 157  /* 64*157 = 10048 >= 10000 */

// ---------------- scratch (static device memory; no runtime allocs) ----------
__device__ __align__(16) float g_bufA[(size_t)MM * DD];
__device__ __align__(16) float g_bufB[(size_t)MM * DD];
__device__ __align__(16) float g_bufC[(size_t)MM * DD];
__device__ int   g_deg[NN];
__device__ int   g_off[NN + 1];
__device__ int   g_cursor[NN];
__device__ int   g_eidx[EE];
__device__ float g_score[MM];
__device__ float g_alpha[MM];
__device__ float g_r[BB * DD];
__device__ float g_rpart[BB * NCHUNK * DD];

// ---------------- CSR build --------------------------------------------------
__global__ void k_zero_csr() {
    int i = blockIdx.x * blockDim.x + threadIdx.x;
    if (i < NN) { g_deg[i] = 0; g_cursor[i] = 0; }
}

__global__ void k_degree(const int* __restrict__ dst, int E) {
    int e = blockIdx.x * blockDim.x + threadIdx.x;
    if (e < E) atomicAdd(&g_deg[dst[e]], 1);
}

// one-block exclusive scan over NN=10000 (1000 threads x 10 elems)
__global__ void k_scan() {
    __shared__ int tsums[1024];
    int t = threadIdx.x;
    int local[10];
    int s = 0;
    if (t < 1000) {
        int base = t * 10;
#pragma unroll
        for (int i = 0; i < 10; i++) { local[i] = g_deg[base + i]; s += local[i]; }
    }
    tsums[t] = (t < 1000) ? s : 0;
    __syncthreads();
    for (int off = 1; off < 1024; off <<= 1) {
        int v = (t >= off) ? tsums[t - off] : 0;
        __syncthreads();
        tsums[t] += v;
        __syncthreads();
    }
    if (t < 1000) {
        int run = (t == 0) ? 0 : tsums[t - 1];
        int base = t * 10;
#pragma unroll
        for (int i = 0; i < 10; i++) { g_off[base + i] = run; run += local[i]; }
    }
    if (t == 0) g_off[NN] = tsums[1023];
}

__global__ void k_fill(const int* __restrict__ src, const int* __restrict__ dst, int E) {
    int e = blockIdx.x * blockDim.x + threadIdx.x;
    if (e < E) {
        int d = dst[e];
        int p = atomicAdd(&g_cursor[d], 1);
        g_eidx[g_off[d] + p] = src[e];
    }
}

// ---------------- generic SGEMM: C = A(MxK) @ B(KxN) [+bias][+relu] ----------
// requires M%64==0, N%64==0, K%16==0
__global__ void k_gemm(const float* __restrict__ A, const float* __restrict__ B,
                       const float* __restrict__ bias, float* __restrict__ C,
                       int M, int N, int K, int act) {
    __shared__ __align__(16) float As[16][64];
    __shared__ __align__(16) float Bs[16][64];
    int bm = blockIdx.y * 64, bn = blockIdx.x * 64;
    int tid = threadIdx.x;
    int tx = tid & 15, ty = tid >> 4;

    const int ar = tid >> 2;            // 0..63  (A row within tile)
    const int ac = (tid & 3) << 2;      // 0,4,8,12 (A col within ktile)
    const int br = tid >> 4;            // 0..15  (B row within ktile)
    const int bc = (tid & 15) << 2;     // 0..60  (B col within tile)

    float acc[4][4] = {};

    for (int k0 = 0; k0 < K; k0 += 16) {
        float4 av = *(const float4*)(A + (size_t)(bm + ar) * K + k0 + ac);
        float4 bv = *(const float4*)(B + (size_t)(k0 + br) * N + bn + bc);
        As[ac + 0][ar] = av.x;
        As[ac + 1][ar] = av.y;
        As[ac + 2][ar] = av.z;
        As[ac + 3][ar] = av.w;
        *(float4*)&Bs[br][bc] = bv;
        __syncthreads();
#pragma unroll
        for (int kk = 0; kk < 16; kk++) {
            float4 a4 = *(const float4*)&As[kk][ty << 2];
            float4 b4 = *(const float4*)&Bs[kk][tx << 2];
            float avv[4] = {a4.x, a4.y, a4.z, a4.w};
            float bvv[4] = {b4.x, b4.y, b4.z, b4.w};
#pragma unroll
            for (int i = 0; i < 4; i++)
#pragma unroll
                for (int j = 0; j < 4; j++) acc[i][j] += avv[i] * bvv[j];
        }
        __syncthreads();
    }

#pragma unroll
    for (int i = 0; i < 4; i++) {
        int row = bm + (ty << 2) + i;
        int col = bn + (tx << 2);
        float o[4];
#pragma unroll
        for (int j = 0; j < 4; j++) {
            float v = acc[i][j];
            if (bias) v += bias[col + j];
            if (act == 1) v = fmaxf(v, 0.0f);
            o[j] = v;
        }
        *(float4*)(C + (size_t)row * N + col) = make_float4(o[0], o[1], o[2], o[3]);
    }
}

// ---------------- GCN aggregation + bias + exact GELU ------------------------
__global__ void k_agg_gelu(const float* __restrict__ sup, const float* __restrict__ bias,
                           float* __restrict__ out) {
    int n = blockIdx.x, b = blockIdx.y, h = threadIdx.x;
    int s = g_off[n], e = g_off[n + 1];
    const float* base = sup + (size_t)b * NN * DD;
    float acc = 0.0f;
    for (int j = s; j < e; j++) acc += base[(size_t)g_eidx[j] * DD + h];
    float v = acc + bias[h];
    out[((size_t)b * NN + n) * DD + h] = 0.5f * v * (1.0f + erff(v * 0.70710678118654752f));
}

// ---------------- attention pool pieces ---------------------------------------
__global__ void k_attn_score(const float* __restrict__ x, const float* __restrict__ W,
                             const float* __restrict__ u) {
    int warp = threadIdx.x >> 5, lane = threadIdx.x & 31;
    int idx = blockIdx.x * 8 + warp;  // < MM
    const float* xr = x + (size_t)idx * DD;
    float acc[8] = {0, 0, 0, 0, 0, 0, 0, 0};
    for (int d = lane; d < DD; d += 32) {
        float xv = xr[d];
#pragma unroll
        for (int k = 0; k < 8; k++) acc[k] += xv * W[d * 8 + k];
    }
#pragma unroll
    for (int k = 0; k < 8; k++)
#pragma unroll
        for (int o = 16; o > 0; o >>= 1) acc[k] += __shfl_xor_sync(0xffffffffu, acc[k], o);
    if (lane == 0) {
        float s = 0.0f;
#pragma unroll
        for (int k = 0; k < 8; k++) s += tanhf(acc[k]) * u[k];
        g_score[idx] = s;
    }
}

__global__ void k_dot_r(const float* __restrict__ x) {
    int warp = threadIdx.x >> 5, lane = threadIdx.x & 31;
    int idx = blockIdx.x * 8 + warp;
    int b = idx / NN;
    const float* xr = x + (size_t)idx * DD;
    const float* rr = g_r + b * DD;
    float acc = 0.0f;
    for (int d = lane; d < DD; d += 32) acc += xr[d] * rr[d];
#pragma unroll
    for (int o = 16; o > 0; o >>= 1) acc += __shfl_xor_sync(0xffffffffu, acc, o);
    if (lane == 0) g_score[idx] = acc;
}

__global__ void k_softmax() {
    int b = blockIdx.x, t = threadIdx.x;
    __shared__ float sh[32];
    const float* sc = g_score + b * NN;

    float m = -1e30f;
    for (int n = t; n < NN; n += 1024) m = fmaxf(m, sc[n]);
#pragma unroll
    for (int o = 16; o > 0; o >>= 1) m = fmaxf(m, __shfl_xor_sync(0xffffffffu, m, o));
    if ((t & 31) == 0) sh[t >> 5] = m;
    __syncthreads();
    float mm = -1e30f;
#pragma unroll
    for (int i = 0; i < 32; i++) mm = fmaxf(mm, sh[i]);
    __syncthreads();

    float s = 0.0f;
    for (int n = t; n < NN; n += 1024) s += expf(sc[n] - mm);
#pragma unroll
    for (int o = 16; o > 0; o >>= 1) s += __shfl_xor_sync(0xffffffffu, s, o);
    if ((t & 31) == 0) sh[t >> 5] = s;
    __syncthreads();
    float tot = 0.0f;
#pragma unroll
    for (int i = 0; i < 32; i++) tot += sh[i];
    float inv = 1.0f / tot;

    for (int n = t; n < NN; n += 1024) g_alpha[b * NN + n] = expf(sc[n] - mm) * inv;
}

__global__ void k_wsum(const float* __restrict__ x, int use_alpha) {
    int c = blockIdx.x, b = blockIdx.y, d = threadIdx.x;
    int n0 = c * CHUNK_SZ;
    int n1 = n0 + CHUNK_SZ;
    if (n1 > NN) n1 = NN;
    float acc = 0.0f;
    for (int n = n0; n < n1; n++) {
        float w = use_alpha ? g_alpha[b * NN + n] : 1.0f;
        acc += w * x[((size_t)b * NN + n) * DD + d];
    }
    g_rpart[((size_t)b * NCHUNK + c) * DD + d] = acc;
}

__global__ void k_reduce_r(float scale) {
    int b = blockIdx.x, d = threadIdx.x;
    float s = 0.0f;
    for (int c = 0; c < NCHUNK; c++) s += g_rpart[((size_t)b * NCHUNK + c) * DD + d];
    g_r[b * DD + d] = s * scale;
}

// ---------------- add + layernorm ---------------------------------------------
__device__ __forceinline__ float blk_sum256(float v) {
    __shared__ float sh[8];
#pragma unroll
    for (int o = 16; o > 0; o >>= 1) v += __shfl_xor_sync(0xffffffffu, v, o);
    if ((threadIdx.x & 31) == 0) sh[threadIdx.x >> 5] = v;
    __syncthreads();
    float t = 0.0f;
#pragma unroll
    for (int i = 0; i < 8; i++) t += sh[i];
    __syncthreads();
    return t;
}

__global__ void k_add_ln(const float* __restrict__ x, const float* __restrict__ h, int use_r,
                         const float* __restrict__ g, const float* __restrict__ bb,
                         float* __restrict__ out) {
    int idx = blockIdx.x;
    int b = idx / NN;
    int d = threadIdx.x;
    float addv;
    if (use_r) addv = g_r[b * DD + d];
    else       addv = h[(size_t)idx * DD + d];
    float v = x[(size_t)idx * DD + d] + addv;
    float mu = blk_sum256(v) * (1.0f / DD);
    float dv = v - mu;
    float var = blk_sum256(dv * dv) * (1.0f / DD);
    out[(size_t)idx * DD + d] = dv * rsqrtf(var + 1e-5f) * g[d] + bb[d];
}

// ---------------- final FC on mean(x) ------------------------------------------
__global__ void k_fc(const float* __restrict__ fcW, const float* __restrict__ fcb,
                     float* __restrict__ out) {
    int t = threadIdx.x;
    if (t < BB * 10) {
        int b = t / 10, o = t % 10;
        float s = fcb[o];
        for (int d = 0; d < DD; d++) s += g_r[b * DD + d] * fcW[d * 10 + o];
        out[t] = s;
    }
}

// ---------------- launch ---------------------------------------------------------
extern "C" void kernel_launch(void* const* d_in, const int* in_sizes, int n_in,
                              void* d_out, int out_size) {
    const float* x_in    = (const float*)d_in[0];
    const int*   src     = (const int*)d_in[1];
    const int*   dst     = (const int*)d_in[2];
    const float* W_conv0 = (const float*)d_in[3];
    const float* b_conv0 = (const float*)d_in[4];
    const float* W_convs = (const float*)d_in[5];
    const float* b_convs = (const float*)d_in[6];
    const float* mW1 = (const float*)d_in[7];
    const float* mb1 = (const float*)d_in[8];
    const float* mW2 = (const float*)d_in[9];
    const float* mb2 = (const float*)d_in[10];
    const float* mW3 = (const float*)d_in[11];
    const float* mb3 = (const float*)d_in[12];
    const float* ln1_g = (const float*)d_in[13];
    const float* ln1_b = (const float*)d_in[14];
    const float* ln2_g = (const float*)d_in[15];
    const float* ln2_b = (const float*)d_in[16];
    const float* attnW = (const float*)d_in[17];
    const float* attnu = (const float*)d_in[18];
    const float* fW1 = (const float*)d_in[19];
    const float* fb1 = (const float*)d_in[20];
    const float* fW2 = (const float*)d_in[21];
    const float* fb2 = (const float*)d_in[22];
    const float* fcW = (const float*)d_in[23];
    const float* fcb = (const float*)d_in[24];
    float* out = (float*)d_out;
    int E = in_sizes[1];

    float *bufA, *bufB, *bufC;
    cudaGetSymbolAddress((void**)&bufA, g_bufA);
    cudaGetSymbolAddress((void**)&bufB, g_bufB);
    cudaGetSymbolAddress((void**)&bufC, g_bufC);

    // ---- CSR build (by dst) ----
    k_zero_csr<<<(NN + 255) / 256, 256>>>();
    k_degree<<<(E + 255) / 256, 256>>>(dst, E);
    k_scan<<<1, 1024>>>();
    k_fill<<<(E + 255) / 256, 256>>>(src, dst, E);

    dim3 gemm256(256 / 64, MM / 64);
    dim3 gemm128(128 / 64, MM / 64);
    dim3 gemm64(64 / 64, MM / 64);
    dim3 aggGrid(NN, BB);

    // ---- GCN stack ----
    k_gemm<<<gemm256, 256>>>(x_in, W_conv0, nullptr, bufB, MM, 256, 128, 0);
    k_agg_gelu<<<aggGrid, 256>>>(bufB, b_conv0, bufA);
    for (int i = 0; i < 3; i++) {
        k_gemm<<<gemm256, 256>>>(bufA, W_convs + (size_t)i * 256 * 256, nullptr, bufB,
                                 MM, 256, 256, 0);
        k_agg_gelu<<<aggGrid, 256>>>(bufB, b_convs + i * 256, bufA);
    }

    // ---- MLP ----
    k_gemm<<<gemm128, 256>>>(bufA, mW1, mb1, bufB, MM, 128, 256, 1);
    k_gemm<<<gemm64, 256>>>(bufB, mW2, mb2, bufC, MM, 64, 128, 1);
    k_gemm<<<gemm256, 256>>>(bufC, mW3, mb3, bufA, MM, 256, 64, 0);

    // ---- 2 pooled residual blocks ----
    float* cur = bufA;
    float* o1 = bufB;
    float* o2 = bufC;
    for (int i = 0; i < 2; i++) {
        // attention pool
        k_attn_score<<<MM / 8, 256>>>(cur, attnW + (size_t)i * DD * 8, attnu + i * 8);
        k_softmax<<<BB, 1024>>>();
        k_wsum<<<dim3(NCHUNK, BB), 256>>>(cur, 1);
        k_reduce_r<<<BB, 256>>>(1.0f);
        for (int it = 0; it < 3; it++) {
            k_dot_r<<<MM / 8, 256>>>(cur);
            k_softmax<<<BB, 1024>>>();
            k_wsum<<<dim3(NCHUNK, BB), 256>>>(cur, 1);
            k_reduce_r<<<BB, 256>>>(1.0f);
        }
        // x = LN(x + r)
        k_add_ln<<<MM, 256>>>(cur, cur /*unused*/, 1, ln1_g + i * DD, ln1_b + i * DD, o1);
        // FFN
        k_gemm<<<gemm256, 256>>>(o1, fW1 + (size_t)i * DD * 256, fb1 + i * 256, o2,
                                 MM, 256, 256, 1);
        k_gemm<<<gemm256, 256>>>(o2, fW2 + (size_t)i * 256 * DD, fb2 + i * DD, cur,
                                 MM, 256, 256, 0);
        // x = LN(x + h)  — reads o1 (residual) + cur (h), writes o2
        k_add_ln<<<MM, 256>>>(o1, cur, 0, ln2_g + i * DD, ln2_b + i * DD, o2);
        // rotate: new cur = o2, old cur becomes scratch
        float* t = cur; cur = o2; o2 = t;
    }

    // ---- final: out = mean_n(x) @ fcW + fcb ----
    k_wsum<<<dim3(NCHUNK, BB), 256>>>(cur, 0);
    k_reduce_r<<<BB, 256>>>(1.0f / (float)NN);
    k_fc<<<1, 64>>>(fcW, fcb, out);
}